// round 3
// baseline (speedup 1.0000x reference)
#include <cuda_runtime.h>

#define BATCH 8
typedef unsigned long long ull;

// Inter-kernel scratch: hidden activations, layout [BATCH][8192]
__device__ float g_hidden[BATCH * 8192];

__device__ __forceinline__ void fma2(ull &acc, ull a, ull b) {
    // packed fp32x2 FMA (Blackwell): acc.lo += a.lo*b.lo; acc.hi += a.hi*b.hi
    asm volatile("fma.rn.f32x2 %0, %1, %2, %0;" : "+l"(acc) : "l"(a), "l"(b));
}

__device__ __forceinline__ unsigned smem_u32(const void* p) {
    return (unsigned)__cvta_generic_to_shared(p);
}

__device__ __forceinline__ void cp_async16(unsigned dst, const void* src) {
    asm volatile("cp.async.ca.shared.global [%0], [%1], 16;" :: "r"(dst), "l"(src) : "memory");
}

// out[b*HSTRIDE + row] = act( sum_k W[row,k]*in[b,k] + bias[row] )
// in = concat(inA [BATCH, splitK], inB [BATCH, K-splitK]); inA==nullptr -> g_hidden.
template<int K, int RPW, int WARPS, int CHUNK, int HSTRIDE, bool TANH>
__global__ void __launch_bounds__(WARPS * 32, 4) gemv_kernel(
    const float* __restrict__ W,
    const float* __restrict__ inA,
    const float* __restrict__ inB,
    int splitK,
    const float* __restrict__ bias,
    float* __restrict__ out)
{
    constexpr int NCH = K / CHUNK;
    constexpr int RPB = RPW * WARPS;
    static_assert(RPW * BATCH == 32, "one lane per (row,batch) output");

    __shared__ float s_in[2][BATCH][CHUNK];

    const int tid  = threadIdx.x;
    const int lane = tid & 31;
    const int warp = tid >> 5;
    const int row0 = blockIdx.x * RPB + warp * RPW;

    const float* srcA = inA ? inA : (const float*)g_hidden;
    float* dst = TANH ? (float*)g_hidden : out;

    auto prefetch = [&](int buf, int c) {
        const int k0 = c * CHUNK;
        constexpr int NV = BATCH * CHUNK / 4;   // float4 transfers
        #pragma unroll
        for (int i = tid; i < NV; i += WARPS * 32) {
            int b  = i / (CHUNK / 4);
            int kk = (i % (CHUNK / 4)) * 4;
            int kg = k0 + kk;
            const float* src = (kg < splitK)
                ? (srcA + (size_t)b * splitK + kg)
                : (inB  + (size_t)b * (K - splitK) + (kg - splitK));
            cp_async16(smem_u32(&s_in[buf][b][kk]), src);
        }
        asm volatile("cp.async.commit_group;" ::: "memory");
    };

    ull acc[RPW][BATCH];
    #pragma unroll
    for (int r = 0; r < RPW; r++)
        #pragma unroll
        for (int b = 0; b < BATCH; b++)
            acc[r][b] = 0ull;

    prefetch(0, 0);
    if (NCH > 1) prefetch(1, 1);

    for (int c = 0; c < NCH; c++) {
        if (c + 1 < NCH) asm volatile("cp.async.wait_group 1;" ::: "memory");
        else             asm volatile("cp.async.wait_group 0;" ::: "memory");
        __syncthreads();

        const float* wbase = W + (size_t)row0 * K + c * CHUNK;
        const float* sbase = &s_in[c & 1][0][0];

        #pragma unroll
        for (int s = 0; s < CHUNK / 64; s++) {
            const int kk = s * 64 + lane * 2;
            ull w[RPW];
            #pragma unroll
            for (int r = 0; r < RPW; r++)
                w[r] = __ldcs((const ull*)(wbase + (size_t)r * K + kk));
            ull iv[BATCH];
            #pragma unroll
            for (int b = 0; b < BATCH; b++)
                iv[b] = *(const ull*)(sbase + b * CHUNK + kk);
            #pragma unroll
            for (int r = 0; r < RPW; r++)
                #pragma unroll
                for (int b = 0; b < BATCH; b++)
                    fma2(acc[r][b], w[r], iv[b]);
        }
        __syncthreads();
        if (c + 2 < NCH) prefetch(c & 1, c + 2);
    }

    // Cross-lane reduce: lane (r*8+b) ends owning output (row0+r, batch b).
    float myval = 0.f;
    #pragma unroll
    for (int r = 0; r < RPW; r++) {
        #pragma unroll
        for (int b = 0; b < BATCH; b++) {
            float v = __uint_as_float((unsigned)(acc[r][b] & 0xffffffffu))
                    + __uint_as_float((unsigned)(acc[r][b] >> 32));
            #pragma unroll
            for (int off = 16; off; off >>= 1)
                v += __shfl_xor_sync(0xffffffffu, v, off);
            if (lane == r * BATCH + b) myval = v;
        }
    }
    {
        const int r   = lane / BATCH;
        const int b   = lane % BATCH;
        const int row = row0 + r;
        float v = myval + bias[row];
        if (TANH) v = tanhf(v);
        dst[(size_t)b * HSTRIDE + row] = v;
    }
}

extern "C" void kernel_launch(void* const* d_in, const int* in_sizes, int n_in,
                              void* d_out, int out_size) {
    const float* x     = (const float*)d_in[0];   // [8, 8192]
    const float* h0    = (const float*)d_in[1];   // [8, 8192]
    const float* w_i2h = (const float*)d_in[2];   // [8192, 16384]
    const float* b_i2h = (const float*)d_in[3];   // [8192]
    const float* w_h2o = (const float*)d_in[4];   // [2048, 8192]
    const float* b_h2o = (const float*)d_in[5];   // [2048]
    float* out = (float*)d_out;                   // [8, 2048]

    // Kernel 1: g_hidden = tanh(x@Wx^T + h0@Wh^T + b).  8192 rows / 16 = 512 blocks.
    gemv_kernel<16384, 4, 4, 512, 8192, true><<<512, 128>>>(
        w_i2h, x, h0, 8192, b_i2h, nullptr);

    // Kernel 2: out = g_hidden@Wo^T + b.  2048 rows / 16 = 128 blocks.
    gemv_kernel<8192, 4, 4, 512, 2048, false><<<128, 128>>>(
        w_h2o, nullptr, nullptr, 8192, b_h2o, out);
}

// round 8
// speedup vs baseline: 1.1285x; 1.1285x over previous
#include <cuda_runtime.h>

#define BATCH 8
typedef unsigned long long ull;

// Inter-kernel scratch (no allocations allowed). These symbols are ONLY
// referenced from device code — passing a __device__ symbol as a host-side
// kernel argument yields the host shadow address (the R5 bug).
__device__ float g_hidden[BATCH * 8192];            // [batch][8192]
__device__ float g_part[4 * BATCH * 8192];          // [split][batch][row]

__device__ __forceinline__ void fma2(ull &acc, ull a, ull b) {
    // packed fp32x2 FMA (Blackwell): acc.lo += a.lo*b.lo; acc.hi += a.hi*b.hi
    asm volatile("fma.rn.f32x2 %0, %1, %2, %0;" : "+l"(acc) : "l"(a), "l"(b));
}

__device__ __forceinline__ unsigned smem_u32(const void* p) {
    return (unsigned)__cvta_generic_to_shared(p);
}

__device__ __forceinline__ void cp_async16(unsigned dst, const void* src) {
    asm volatile("cp.async.ca.shared.global [%0], [%1], 16;" :: "r"(dst), "l"(src) : "memory");
}

// Split-K GEMV partial:
//   g_part[(blockIdx.y*BATCH + b)*ROWS + row] = sum_{k in split's KC chunk} W[row,k]*in[b,k]
// in = concat(inA [BATCH, splitK], inB [BATCH, KFULL-splitK]); inA==nullptr -> g_hidden.
// Grid: x = row tiles (ROWS/(RPW*WARPS)), y = split index (KFULL/KC).
template<int KFULL, int KC, int RPW, int WARPS, int CHUNK, int ROWS>
__global__ void __launch_bounds__(WARPS * 32, 3) gemv_partial_kernel(
    const float* __restrict__ W,
    const float* __restrict__ inA,
    const float* __restrict__ inB,
    int splitK)
{
    constexpr int NCH = KC / CHUNK;
    constexpr int RPB = RPW * WARPS;
    static_assert(RPW * BATCH == 32, "one lane per (row,batch) output");

    __shared__ float s_in[2][BATCH][CHUNK];

    const int tid  = threadIdx.x;
    const int lane = tid & 31;
    const int warp = tid >> 5;
    const int row0 = blockIdx.x * RPB + warp * RPW;
    const int koff = blockIdx.y * KC;

    const float* srcA = inA ? inA : (const float*)g_hidden;

    auto prefetch = [&](int buf, int c) {
        const int k0 = koff + c * CHUNK;
        constexpr int NV = BATCH * CHUNK / 4;   // float4 transfers
        #pragma unroll
        for (int i = tid; i < NV; i += WARPS * 32) {
            int b  = i / (CHUNK / 4);
            int kk = (i % (CHUNK / 4)) * 4;
            int kg = k0 + kk;
            const float* src = (kg < splitK)
                ? (srcA + (size_t)b * splitK + kg)
                : (inB  + (size_t)b * (KFULL - splitK) + (kg - splitK));
            cp_async16(smem_u32(&s_in[buf][b][kk]), src);
        }
        asm volatile("cp.async.commit_group;" ::: "memory");
    };

    ull acc[RPW][BATCH];
    #pragma unroll
    for (int r = 0; r < RPW; r++)
        #pragma unroll
        for (int b = 0; b < BATCH; b++)
            acc[r][b] = 0ull;

    prefetch(0, 0);
    if (NCH > 1) prefetch(1, 1);

    for (int c = 0; c < NCH; c++) {
        if (c + 1 < NCH) asm volatile("cp.async.wait_group 1;" ::: "memory");
        else             asm volatile("cp.async.wait_group 0;" ::: "memory");
        __syncthreads();

        const float* wbase = W + (size_t)row0 * KFULL + koff + c * CHUNK;
        const float* sbase = &s_in[c & 1][0][0];

        // Each step covers 128 k per warp: lane owns 4 consecutive k.
        // 8 independent LDG.64s are front-batched per step -> 2 KB/warp in
        // flight; 12 resident warps/SM -> ~24 KB, above the ~18 KB
        // BW-latency product needed to saturate HBM.
        #pragma unroll
        for (int s = 0; s < CHUNK / 128; s++) {
            const int kk = s * 128 + lane * 4;
            ull wA[RPW], wB[RPW];
            #pragma unroll
            for (int r = 0; r < RPW; r++) {
                const ull* p = (const ull*)(wbase + (size_t)r * KFULL + kk);
                wA[r] = __ldcs(p);
                wB[r] = __ldcs(p + 1);
            }
            #pragma unroll
            for (int b = 0; b < BATCH; b++) {
                ull ivA = *(const ull*)(sbase + b * CHUNK + kk);
                ull ivB = *(const ull*)(sbase + b * CHUNK + kk + 2);
                #pragma unroll
                for (int r = 0; r < RPW; r++) {
                    fma2(acc[r][b], wA[r], ivA);
                    fma2(acc[r][b], wB[r], ivB);
                }
            }
        }
        __syncthreads();
        if (c + 2 < NCH) prefetch(c & 1, c + 2);
    }

    // Cross-lane reduce: lane (r*8+b) ends owning partial (row0+r, batch b).
    float myval = 0.f;
    #pragma unroll
    for (int r = 0; r < RPW; r++) {
        #pragma unroll
        for (int b = 0; b < BATCH; b++) {
            float v = __uint_as_float((unsigned)(acc[r][b] & 0xffffffffu))
                    + __uint_as_float((unsigned)(acc[r][b] >> 32));
            #pragma unroll
            for (int off = 16; off; off >>= 1)
                v += __shfl_xor_sync(0xffffffffu, v, off);
            if (lane == r * BATCH + b) myval = v;
        }
    }
    {
        const int r   = lane / BATCH;
        const int b   = lane % BATCH;
        const int row = row0 + r;
        g_part[((size_t)blockIdx.y * BATCH + b) * ROWS + row] = myval;
    }
}

// dst[b*ROWS + row] = act( sum_s g_part[(s*BATCH+b)*ROWS + row] + bias[row] )
// TANH=true -> dst = g_hidden (device symbol); TANH=false -> dst = out arg.
template<int ROWS, int S, bool TANH>
__global__ void reduce_kernel(const float* __restrict__ bias,
                              float* __restrict__ out)
{
    int i = blockIdx.x * blockDim.x + threadIdx.x;
    if (i >= BATCH * ROWS) return;
    int b   = i / ROWS;
    int row = i % ROWS;
    float v = bias[row];
    #pragma unroll
    for (int s = 0; s < S; s++)
        v += g_part[((size_t)s * BATCH + b) * ROWS + row];
    if (TANH) v = tanhf(v);
    float* dst = TANH ? (float*)g_hidden : out;
    dst[i] = v;
}

extern "C" void kernel_launch(void* const* d_in, const int* in_sizes, int n_in,
                              void* d_out, int out_size) {
    const float* x     = (const float*)d_in[0];   // [8, 8192]
    const float* h0    = (const float*)d_in[1];   // [8, 8192]
    const float* w_i2h = (const float*)d_in[2];   // [8192, 16384]
    const float* b_i2h = (const float*)d_in[3];   // [8192]
    const float* w_h2o = (const float*)d_in[4];   // [2048, 8192]
    const float* b_h2o = (const float*)d_in[5];   // [2048]
    float* out = (float*)d_out;                   // [8, 2048]

    // Kernel 1 partials: KFULL=16384, 4 splits of 4096. Grid (512, 4).
    gemv_partial_kernel<16384, 4096, 4, 4, 512, 8192><<<dim3(512, 4), 128>>>(
        w_i2h, x, h0, 8192);

    // g_hidden = tanh(sum of partials + bias)
    reduce_kernel<8192, 4, true><<<(BATCH * 8192 + 255) / 256, 256>>>(
        b_i2h, nullptr);

    // Kernel 2 partials: KFULL=8192, 4 splits of 2048. Grid (128, 4).
    // inA=nullptr -> g_hidden; splitK=KFULL so inB (dummy) never dereferenced.
    gemv_partial_kernel<8192, 2048, 4, 4, 512, 2048><<<dim3(128, 4), 128>>>(
        w_h2o, nullptr, x /*unused*/, 8192);

    // out = sum of partials + bias
    reduce_kernel<2048, 4, false><<<(BATCH * 2048 + 255) / 256, 256>>>(
        b_h2o, out);

    (void)in_sizes; (void)n_in; (void)out_size;
}